// round 6
// baseline (speedup 1.0000x reference)
#include <cuda_runtime.h>

// NTM memory read: single pass over the 128MB `memory` tensor with a
// cp.async double-buffered smem pipeline. Global streaming is fully decoupled
// from the per-row score chain (shfl-reduce + rsqrt + exp), which previously
// capped MLP and held HBM at ~56%. In-kernel last-block finalization.
//
// read[b,m] = (Σ_n e_n·z_n·memory[b,n,m]) / (Σ_n e_n)
//           + ((Σ_n e_n·w_w_n) / (Σ_n e_n)) · k[b,m]
// e_n = exp(cos(mem[b,n,:], k[b,:])), z_n = 1-w_lu_prev,
// w_w = g·w_r_prev + (1-g)·w_lu_prev.  cos ∈ [-1,1] -> exp safe without
// max-subtraction. The w_u/sort/gamma branch is dead code for `read`.
// rsqrt(max(sq,1e-16)) == 1/max(norm,1e-8) exactly.

#define NB    64
#define NN    2048
#define NM    256
#define TPB   128
#define NWARP 4
#define BLPB  16                      // blocks per batch -> grid 1024 (one wave @7/SM)
#define RPB   (NN / BLPB)             // 128 rows per block
#define TROWS 8                       // rows per pipeline tile (8 KB)
#define NT    (RPB / TROWS)           // 16 tiles
#define TF4   (TROWS * NM / 4)        // 512 float4 per tile
#define CPT   (TF4 / TPB)             // 4 cp.async per thread per tile
#define FULL  0xffffffffu

__device__ float g_acc[NB][BLPB][NM];   // 1 MB partials
__device__ float g_se[NB][BLPB];
__device__ float g_sw[NB][BLPB];
__device__ int   g_cnt[NB];             // zero-init; reset by finalizing block

__device__ __forceinline__ void cp16(void* s, const void* g) {
    unsigned sa = (unsigned)__cvta_generic_to_shared(s);
    asm volatile("cp.async.cg.shared.global [%0], [%1], 16;" :: "r"(sa), "l"(g));
}
__device__ __forceinline__ float bfly32(float v) {
    #pragma unroll
    for (int off = 16; off; off >>= 1) v += __shfl_xor_sync(FULL, v, off);
    return v;
}

__global__ void __launch_bounds__(TPB, 7)
ntm_fused(const float* __restrict__ mem,
          const float* __restrict__ kk,
          const float* __restrict__ gg,
          const float* __restrict__ w_prev,
          const int*   __restrict__ w_lu,
          float*       __restrict__ out)
{
    const int b    = blockIdx.y;
    const int blk  = blockIdx.x;
    const int tid  = threadIdx.x;
    const int warp = tid >> 5;
    const int lane = tid & 31;
    const bool lo  = lane < 16;

    __shared__ float4 stage[2][TF4];                 // 16 KB staging ring
    __shared__ float  s_acc[NWARP][NM];              // 4 KB block-reduce
    __shared__ float  s_se[NWARP], s_sw[NWARP];
    __shared__ int    s_last;
    __shared__ float  s_invden, s_sfac;

    const int row0 = blk * RPB;                      // block's first row
    const float4* gbase = reinterpret_cast<const float4*>(
        mem + ((size_t)b * NN + row0) * NM);

    // --- prime the pipeline: tile 0 -> stage 0 ---
    #pragma unroll
    for (int i = 0; i < CPT; i++)
        cp16(&stage[0][tid + i * TPB], gbase + tid + i * TPB);
    asm volatile("cp.async.commit_group;");

    // --- k vector: lane owns float4 slots {lane, 32+lane} (cols 4l.., 128+4l..) ---
    const float4* k4 = reinterpret_cast<const float4*>(kk + (size_t)b * NM);
    const float4 ka = k4[lane];
    const float4 kb = k4[32 + lane];
    float ksq = ka.x*ka.x + ka.y*ka.y + ka.z*ka.z + ka.w*ka.w
              + kb.x*kb.x + kb.y*kb.y + kb.z*kb.z + kb.w*kb.w;
    const float inv_knrm = __frsqrt_rn(fmaxf(bfly32(ksq), 1e-16f));

    // --- row metadata. Warp w processes seq s=2t+j -> row_in_block (s>>1)*TROWS + 2w + (s&1).
    //     Lane l is designated seq l. ---
    const int   myrow = ((lane >> 1) * TROWS) + (warp << 1) + (lane & 1);
    const float gb    = gg[b];
    const float wluf  = (float)w_lu[(size_t)b * NN + row0 + myrow];
    const float ww_l  = gb * w_prev[(size_t)b * 2 * NN + NN + row0 + myrow]
                      + (1.0f - gb) * wluf;
    const unsigned zmask = __ballot_sync(FULL, wluf == 0.0f);

    float a0=0.f,a1=0.f,a2=0.f,a3=0.f,a4=0.f,a5=0.f,a6=0.f,a7=0.f;
    float e_mine = 0.0f;

    for (int t = 0; t < NT; t++) {
        if (t + 1 < NT) {
            const float4* src = gbase + (size_t)(t + 1) * TF4;
            float4* dst = &stage[(t + 1) & 1][0];
            #pragma unroll
            for (int i = 0; i < CPT; i++)
                cp16(dst + tid + i * TPB, src + tid + i * TPB);
            asm volatile("cp.async.commit_group;");
            asm volatile("cp.async.wait_group 1;");
        } else {
            asm volatile("cp.async.wait_group 0;");
        }
        __syncthreads();

        const float4* sm = &stage[t & 1][0];
        #pragma unroll
        for (int j = 0; j < 2; j++) {
            const float4* rp = sm + (size_t)((warp << 1) | j) * (NM / 4);
            const float4 va = rp[lane];
            const float4 vb = rp[32 + lane];

            float dot = va.x*ka.x + va.y*ka.y + va.z*ka.z + va.w*ka.w
                      + vb.x*kb.x + vb.y*kb.y + vb.z*kb.z + vb.w*kb.w;
            float sq  = va.x*va.x + va.y*va.y + va.z*va.z + va.w*va.w
                      + vb.x*vb.x + vb.y*vb.y + vb.z*vb.z + vb.w*vb.w;

            // 7-shfl paired reduction: both full sums on every lane.
            dot += __shfl_xor_sync(FULL, dot, 16);
            sq  += __shfl_xor_sync(FULL, sq,  16);
            float c = lo ? dot : sq;
            c += __shfl_xor_sync(FULL, c, 8);
            c += __shfl_xor_sync(FULL, c, 4);
            c += __shfl_xor_sync(FULL, c, 2);
            c += __shfl_xor_sync(FULL, c, 1);
            const float p    = __shfl_xor_sync(FULL, c, 16);
            const float dotf = lo ? c : p;
            const float sqf  = lo ? p : c;

            const float score = dotf * inv_knrm * __frsqrt_rn(fmaxf(sqf, 1e-16f));
            const float e = __expf(score);
            const int   s = (t << 1) | j;
            if (s == lane) e_mine = e;
            const float ez = ((zmask >> s) & 1u) ? e : 0.0f;

            a0 += ez * va.x;  a1 += ez * va.y;  a2 += ez * va.z;  a3 += ez * va.w;
            a4 += ez * vb.x;  a5 += ez * vb.y;  a6 += ez * vb.z;  a7 += ez * vb.w;
        }
        if (t + 1 < NT) __syncthreads();   // stage (t&1) free for tile t+2's prefetch
    }

    // --- warp scalar sums (e_mine covers this warp's 32 rows bijectively) ---
    const float se = bfly32(e_mine);
    const float sw = bfly32(e_mine * ww_l);

    // ---- block-level reduction through smem ----
    __syncthreads();   // all tile compute done before s_acc overwrites concerns (distinct smem, but order anyway)
    float4* sa = reinterpret_cast<float4*>(&s_acc[warp][0]);
    sa[lane]      = make_float4(a0, a1, a2, a3);
    sa[32 + lane] = make_float4(a4, a5, a6, a7);
    if (lane == 0) { s_se[warp] = se; s_sw[warp] = sw; }
    __syncthreads();

    float b0 = 0.f, b1 = 0.f;
    #pragma unroll
    for (int w = 0; w < NWARP; w++) { b0 += s_acc[w][tid]; b1 += s_acc[w][tid + 128]; }
    g_acc[b][blk][tid]       = b0;
    g_acc[b][blk][tid + 128] = b1;
    if (tid == 0) {
        float bse = 0.f, bsw = 0.f;
        #pragma unroll
        for (int w = 0; w < NWARP; w++) { bse += s_se[w]; bsw += s_sw[w]; }
        g_se[b][blk] = bse;
        g_sw[b][blk] = bsw;
    }

    // ---- last block per batch finalizes (deterministic fixed-order sums) ----
    __threadfence();
    if (tid == 0) {
        int old = atomicAdd(&g_cnt[b], 1);
        s_last = (old == BLPB - 1);
    }
    __syncthreads();
    if (!s_last) return;

    float f0 = 0.f, f1 = 0.f;
    #pragma unroll
    for (int w = 0; w < BLPB; w++) { f0 += g_acc[b][w][tid]; f1 += g_acc[b][w][tid + 128]; }

    if (tid == 0) {
        float fse = 0.f, fsw = 0.f;
        #pragma unroll
        for (int w = 0; w < BLPB; w++) { fse += g_se[b][w]; fsw += g_sw[b][w]; }
        s_invden = 1.0f / fse;
        s_sfac   = fsw / fse;
        g_cnt[b] = 0;                      // reset for next graph replay
    }
    __syncthreads();

    const float* kb2 = kk + (size_t)b * NM;
    out[(size_t)b * NM + tid]       = f0 * s_invden + s_sfac * kb2[tid];
    out[(size_t)b * NM + tid + 128] = f1 * s_invden + s_sfac * kb2[tid + 128];
}

extern "C" void kernel_launch(void* const* d_in, const int* in_sizes, int n_in,
                              void* d_out, int out_size)
{
    const float* mem    = (const float*)d_in[0];  // [B,N,M] f32
    const float* k      = (const float*)d_in[1];  // [B,M]   f32
    const float* g      = (const float*)d_in[2];  // [B,1]   f32
    // d_in[3] = gamma, d_in[6] = n : dead for the output
    const float* w_prev = (const float*)d_in[4];  // [B,2,N] f32
    const int*   w_lu   = (const int*)  d_in[5];  // [B,N]   i32
    float*       out    = (float*)d_out;          // [B,M]   f32

    dim3 grid(BLPB, NB);
    ntm_fused<<<grid, TPB>>>(mem, k, g, w_prev, w_lu, out);
}